// round 3
// baseline (speedup 1.0000x reference)
#include <cuda_runtime.h>

#define Bc 8
#define Sc 1024
#define DMc 512
#define Hc 8
#define Dc 64

// ---------------- device scratch (allowed: __device__ globals) ----------------
__device__ float g_Q[Bc*Hc*Sc*Dc];                 // 16 MB, [B,H,S,64]
__device__ float g_K[Bc*Hc*Sc*Dc];                 // 16 MB
__device__ float g_V[Bc*Hc*Sc*Dc];                 // 16 MB
__device__ float g_ctx[Bc*Sc*DMc];                 // 16 MB, [B,S,512]
__device__ float g_scores[Bc*Hc*Sc*Sc];            // 256 MB, [B,H,S,S] (post edge+mask)
__device__ float g_m[Bc*Hc*Sc];                    // row max
__device__ float g_linv[Bc*Hc*Sc];                 // 1/row sumexp

// ---------------- GEMM: C[8192,512] = A[8192,512] @ W[512,512] ----------------
// sel 0/1/2: store remapped into g_Q/g_K/g_V as [B,H,S,64]
// sel 3:     A := g_ctx, plain store into Cplain (d_out part 1)
__global__ __launch_bounds__(256) void gemm_kernel(const float* __restrict__ A,
                                                   const float* __restrict__ W,
                                                   float* __restrict__ Cplain,
                                                   int sel)
{
    __shared__ float As[16][132];
    __shared__ float Bs[16][132];
    const float* Ap = (sel == 3) ? g_ctx : A;

    int tid = threadIdx.x;
    int tx = tid & 15, ty = tid >> 4;
    int m0 = blockIdx.y * 128, n0 = blockIdx.x * 128;

    float acc[8][8];
#pragma unroll
    for (int i = 0; i < 8; i++)
#pragma unroll
        for (int j = 0; j < 8; j++) acc[i][j] = 0.f;

    for (int kt = 0; kt < 512; kt += 16) {
#pragma unroll
        for (int u = 0; u < 8; u++) {           // A tile 128x16 -> As[k][m]
            int e = tid + 256 * u;
            int m = e >> 4, k = e & 15;
            As[k][m] = Ap[(m0 + m) * 512 + kt + k];
        }
#pragma unroll
        for (int u = 0; u < 8; u++) {           // W tile 16x128 -> Bs[k][n]
            int e = tid + 256 * u;
            int k = e >> 7, n = e & 127;
            Bs[k][n] = W[(kt + k) * 512 + n0 + n];
        }
        __syncthreads();
#pragma unroll
        for (int kk = 0; kk < 16; kk++) {
            float a[8], bb[8];
            float4 t;
            t = *(const float4*)&As[kk][ty * 4];      a[0]=t.x; a[1]=t.y; a[2]=t.z; a[3]=t.w;
            t = *(const float4*)&As[kk][64 + ty * 4]; a[4]=t.x; a[5]=t.y; a[6]=t.z; a[7]=t.w;
            t = *(const float4*)&Bs[kk][tx * 4];      bb[0]=t.x; bb[1]=t.y; bb[2]=t.z; bb[3]=t.w;
            t = *(const float4*)&Bs[kk][64 + tx * 4]; bb[4]=t.x; bb[5]=t.y; bb[6]=t.z; bb[7]=t.w;
#pragma unroll
            for (int i = 0; i < 8; i++)
#pragma unroll
                for (int j = 0; j < 8; j++)
                    acc[i][j] += a[i] * bb[j];
        }
        __syncthreads();
    }

    float* dst = (sel == 0) ? g_Q : (sel == 1) ? g_K : (sel == 2) ? g_V : 0;
#pragma unroll
    for (int i = 0; i < 8; i++) {
        int m = m0 + ((i < 4) ? (ty * 4 + i) : (64 + ty * 4 + i - 4));
#pragma unroll
        for (int j = 0; j < 8; j++) {
            int n = n0 + ((j < 4) ? (tx * 4 + j) : (64 + tx * 4 + j - 4));
            float v = acc[i][j];
            if (sel == 3) {
                Cplain[m * 512 + n] = v;
            } else {
                int b = m >> 10, s = m & 1023;
                int h = n >> 6,  d = n & 63;
                dst[((b * Hc + h) * Sc + s) * Dc + d] = v;
            }
        }
    }
}

// ---------------- scores: per (b,h): S = Q K^T /8 + edge, mask -> scratch -----
// grid: (k_tiles=8, q_tiles=8, B*H=64); block 256; tile 128x128, full d=64 staged
__global__ __launch_bounds__(256, 2) void scores_kernel(const float* __restrict__ edge,
                                                        const int* __restrict__ mask)
{
    extern __shared__ float sm[];
    float (*Qs)[132] = (float(*)[132])sm;             // [d][q]
    float (*Ks)[132] = (float(*)[132])(sm + 64 * 132);// [d][k]

    int tid = threadIdx.x;
    int tx = tid & 15, ty = tid >> 4;
    int k0 = blockIdx.x * 128, q0 = blockIdx.y * 128;
    int bh = blockIdx.z;
    int b = bh >> 3;

    const float* Qg = g_Q + (bh * Sc + q0) * Dc;
    const float* Kg = g_K + (bh * Sc + k0) * Dc;
#pragma unroll
    for (int u = 0; u < 32; u++) {                    // 8192 elems each side
        int e = tid + 256 * u;
        int r = e >> 6, d = e & 63;
        Qs[d][r] = Qg[r * 64 + d];
        Ks[d][r] = Kg[r * 64 + d];
    }
    __syncthreads();

    float acc[8][8];
#pragma unroll
    for (int i = 0; i < 8; i++)
#pragma unroll
        for (int j = 0; j < 8; j++) acc[i][j] = 0.f;

#pragma unroll 16
    for (int dd = 0; dd < 64; dd++) {
        float a[8], bb[8];
        float4 t;
        t = *(const float4*)&Qs[dd][ty * 4];      a[0]=t.x; a[1]=t.y; a[2]=t.z; a[3]=t.w;
        t = *(const float4*)&Qs[dd][64 + ty * 4]; a[4]=t.x; a[5]=t.y; a[6]=t.z; a[7]=t.w;
        t = *(const float4*)&Ks[dd][tx * 4];      bb[0]=t.x; bb[1]=t.y; bb[2]=t.z; bb[3]=t.w;
        t = *(const float4*)&Ks[dd][64 + tx * 4]; bb[4]=t.x; bb[5]=t.y; bb[6]=t.z; bb[7]=t.w;
#pragma unroll
        for (int i = 0; i < 8; i++)
#pragma unroll
            for (int j = 0; j < 8; j++)
                acc[i][j] += a[i] * bb[j];
    }

#pragma unroll
    for (int i = 0; i < 8; i++) {
        int q = q0 + ((i < 4) ? (ty * 4 + i) : (64 + ty * 4 + i - 4));
        int rowe = (b * Sc + q) * Sc;
        int rows = (bh * Sc + q) * Sc;
#pragma unroll
        for (int g = 0; g < 2; g++) {
            int k = k0 + g * 64 + tx * 4;
            float4 ev = *(const float4*)&edge[rowe + k];
            int4   mv = *(const int4*)&mask[rowe + k];
            int jb = g * 4;
            float4 o;
            o.x = mv.x ? -1e9f : acc[i][jb + 0] * 0.125f + ev.x;
            o.y = mv.y ? -1e9f : acc[i][jb + 1] * 0.125f + ev.y;
            o.z = mv.z ? -1e9f : acc[i][jb + 2] * 0.125f + ev.z;
            o.w = mv.w ? -1e9f : acc[i][jb + 3] * 0.125f + ev.w;
            *(float4*)&g_scores[rows + k] = o;
        }
    }
}

// ---------------- row stats (max, 1/sumexp) + head-avg -> d_out part 2 --------
__global__ __launch_bounds__(256) void rowstats_kernel(float* __restrict__ out_avg)
{
    __shared__ float red[8];
    int tid = threadIdx.x;
    int bq = blockIdx.x;              // b*S + q
    int b = bq >> 10, q = bq & 1023;
    int lane = tid & 31, wid = tid >> 5;

    float4 av = make_float4(0.f, 0.f, 0.f, 0.f);
#pragma unroll 1
    for (int h = 0; h < 8; h++) {
        int row = (b * 8 + h) * 1024 + q;
        float4 v = *(const float4*)&g_scores[row * 1024 + tid * 4];

        float mx = fmaxf(fmaxf(v.x, v.y), fmaxf(v.z, v.w));
#pragma unroll
        for (int o = 16; o; o >>= 1) mx = fmaxf(mx, __shfl_xor_sync(0xffffffffu, mx, o));
        if (lane == 0) red[wid] = mx;
        __syncthreads();
        mx = red[0];
#pragma unroll
        for (int w = 1; w < 8; w++) mx = fmaxf(mx, red[w]);
        __syncthreads();

        float se = expf(v.x - mx) + expf(v.y - mx) + expf(v.z - mx) + expf(v.w - mx);
#pragma unroll
        for (int o = 16; o; o >>= 1) se += __shfl_xor_sync(0xffffffffu, se, o);
        if (lane == 0) red[wid] = se;
        __syncthreads();
        se = red[0] + red[1] + red[2] + red[3] + red[4] + red[5] + red[6] + red[7];
        __syncthreads();

        if (tid == 0) { g_m[row] = mx; g_linv[row] = 1.0f / se; }
        av.x += v.x; av.y += v.y; av.z += v.z; av.w += v.w;
    }
    av.x *= 0.125f; av.y *= 0.125f; av.z *= 0.125f; av.w *= 0.125f;
    *(float4*)&out_avg[bq * 1024 + tid * 4] = av;
}

// ---------------- AV: ctx[b,q, h*64+d] = softmax(S) @ V ----------------------
// grid: (q_tiles=4 [256 rows each], B*H=64); block 256
__global__ __launch_bounds__(256, 2) void av_kernel()
{
    extern __shared__ float sm[];
    float (*Ps)[260] = (float(*)[260])sm;               // [k][q], 64x260
    float (*Vs)[68]  = (float(*)[68])(sm + 64 * 260);   // [k][d], 64x68
    float* ms = sm + 64 * 260 + 64 * 68;                // [256]
    float* ls = ms + 256;                               // [256]

    int tid = threadIdx.x;
    int tx = tid & 15, ty = tid >> 4;
    int q0 = blockIdx.x * 256;
    int bh = blockIdx.y;
    int b = bh >> 3, h = bh & 7;

    if (tid < 256) {
        ms[tid] = g_m[bh * 1024 + q0 + tid];
        ls[tid] = g_linv[bh * 1024 + q0 + tid];
    }
    __syncthreads();

    float acc[16][4];
#pragma unroll
    for (int i = 0; i < 16; i++)
#pragma unroll
        for (int j = 0; j < 4; j++) acc[i][j] = 0.f;

    for (int kt = 0; kt < 1024; kt += 64) {
#pragma unroll 8
        for (int u = 0; u < 64; u++) {                  // 256q x 64k
            int e = tid + 256 * u;
            int q = e >> 6, k = e & 63;
            float s = g_scores[(bh * 1024 + q0 + q) * 1024 + kt + k];
            Ps[k][q] = expf(s - ms[q]) * ls[q];
        }
#pragma unroll
        for (int u = 0; u < 16; u++) {                  // 64k x 64d
            int e = tid + 256 * u;
            int k = e >> 6, d = e & 63;
            Vs[k][d] = g_V[(bh * 1024 + kt + k) * 64 + d];
        }
        __syncthreads();
#pragma unroll 8
        for (int kk = 0; kk < 64; kk++) {
            float a[16], bb[4];
            float4 t;
            t = *(const float4*)&Ps[kk][ty * 4];        a[0]=t.x; a[1]=t.y; a[2]=t.z; a[3]=t.w;
            t = *(const float4*)&Ps[kk][64 + ty * 4];   a[4]=t.x; a[5]=t.y; a[6]=t.z; a[7]=t.w;
            t = *(const float4*)&Ps[kk][128 + ty * 4];  a[8]=t.x; a[9]=t.y; a[10]=t.z; a[11]=t.w;
            t = *(const float4*)&Ps[kk][192 + ty * 4];  a[12]=t.x; a[13]=t.y; a[14]=t.z; a[15]=t.w;
            t = *(const float4*)&Vs[kk][tx * 4];        bb[0]=t.x; bb[1]=t.y; bb[2]=t.z; bb[3]=t.w;
#pragma unroll
            for (int i = 0; i < 16; i++)
#pragma unroll
                for (int j = 0; j < 4; j++)
                    acc[i][j] += a[i] * bb[j];
        }
        __syncthreads();
    }

#pragma unroll
    for (int i = 0; i < 16; i++) {
        int g = i >> 2;
        int q = q0 + g * 64 + ty * 4 + (i & 3);
        float4 o = make_float4(acc[i][0], acc[i][1], acc[i][2], acc[i][3]);
        *(float4*)&g_ctx[(b * 1024 + q) * 512 + h * 64 + tx * 4] = o;
    }
}

// ---------------- launch ------------------------------------------------------
extern "C" void kernel_launch(void* const* d_in, const int* in_sizes, int n_in,
                              void* d_out, int out_size)
{
    (void)in_sizes; (void)n_in; (void)out_size;
    const float* inQ  = (const float*)d_in[0];
    const float* inK  = (const float*)d_in[1];
    const float* inV  = (const float*)d_in[2];
    const int*   mask = (const int*)d_in[3];
    const float* edge = (const float*)d_in[4];
    const float* WQ   = (const float*)d_in[5];
    const float* WK   = (const float*)d_in[6];
    const float* WV   = (const float*)d_in[7];
    const float* Wfc  = (const float*)d_in[8];

    float* out     = (float*)d_out;
    float* out_avg = out + Bc * Sc * DMc;

    const int SCORES_SMEM = 2 * 64 * 132 * 4;                       // 67584
    const int AV_SMEM     = (64 * 260 + 64 * 68 + 512) * 4;        // 86016
    cudaFuncSetAttribute(scores_kernel, cudaFuncAttributeMaxDynamicSharedMemorySize, SCORES_SMEM);
    cudaFuncSetAttribute(av_kernel,     cudaFuncAttributeMaxDynamicSharedMemorySize, AV_SMEM);

    dim3 gg(4, 64);
    gemm_kernel<<<gg, 256>>>(inQ, WQ, nullptr, 0);
    gemm_kernel<<<gg, 256>>>(inK, WK, nullptr, 1);
    gemm_kernel<<<gg, 256>>>(inV, WV, nullptr, 2);

    scores_kernel<<<dim3(8, 8, 64), 256, SCORES_SMEM>>>(edge, mask);
    rowstats_kernel<<<8192, 256>>>(out_avg);
    av_kernel<<<dim3(4, 64), 256, AV_SMEM>>>();

    gemm_kernel<<<gg, 256>>>(nullptr, Wfc, out, 3);
}

// round 4
// speedup vs baseline: 1.8141x; 1.8141x over previous
#include <cuda_runtime.h>

#define Bc 8
#define Sc 1024
#define DMc 512
#define Hc 8
#define Dc 64

// ---------------- device scratch ----------------
__device__ float g_Q[Bc*Hc*Sc*Dc];          // [bh][s][d]
__device__ float g_K[Bc*Hc*Sc*Dc];          // [bh][s][d]
__device__ float g_V[Bc*Hc*Sc*Dc];          // [bh][s][d]
__device__ float g_Vt[Bc*Hc*Dc*Sc];         // [bh][d][s]
__device__ float g_ctx[Bc*Sc*DMc];          // [b*s][512]
__device__ float g_Wt[4*DMc*DMc];           // [which][n][k]
__device__ float g_scores[Bc*Hc*Sc*Sc];     // [bh][q][k] (post edge+mask)
__device__ float g_m[Bc*Hc*Sc];
__device__ float g_linv[Bc*Hc*Sc];

__device__ __forceinline__ unsigned f2tf(float x) {
    unsigned u;
    asm("cvt.rna.tf32.f32 %0, %1;" : "=r"(u) : "f"(x));
    return u;
}

__device__ __forceinline__ void mma8(float* c, const unsigned* a, const unsigned* b) {
    asm volatile(
        "mma.sync.aligned.m16n8k8.row.col.f32.tf32.tf32.f32 "
        "{%0,%1,%2,%3}, {%4,%5,%6,%7}, {%8,%9}, {%0,%1,%2,%3};"
        : "+f"(c[0]), "+f"(c[1]), "+f"(c[2]), "+f"(c[3])
        : "r"(a[0]), "r"(a[1]), "r"(a[2]), "r"(a[3]), "r"(b[0]), "r"(b[1]));
}

// ---------------- transpose W: g_Wt[i][n][k] = W_i[k][n] ----------------
__global__ void transpose_w(const float* __restrict__ W0, const float* __restrict__ W1,
                            const float* __restrict__ W2, const float* __restrict__ W3)
{
    __shared__ float t[32][33];
    const float* W = (blockIdx.z == 0) ? W0 : (blockIdx.z == 1) ? W1 : (blockIdx.z == 2) ? W2 : W3;
    float* out = g_Wt + blockIdx.z * DMc * DMc;
    int x0 = blockIdx.x * 32, y0 = blockIdx.y * 32;
    int tx = threadIdx.x, ty = threadIdx.y;
#pragma unroll
    for (int j = 0; j < 32; j += 8) t[ty + j][tx] = W[(y0 + ty + j) * DMc + x0 + tx];
    __syncthreads();
#pragma unroll
    for (int j = 0; j < 32; j += 8) out[(x0 + ty + j) * DMc + y0 + tx] = t[tx][ty + j];
}

// ---------------- transpose V: g_Vt[bh][d][s] = g_V[bh][s][d] ----------------
__global__ void transpose_v()
{
    __shared__ float t[32][33];
    int bh = blockIdx.z;
    int s0 = blockIdx.x * 32, d0 = blockIdx.y * 32;
    const float* V = g_V + bh * Sc * Dc;
    float* Vt = g_Vt + bh * Dc * Sc;
    int tx = threadIdx.x, ty = threadIdx.y;
#pragma unroll
    for (int j = 0; j < 32; j += 8) t[ty + j][tx] = V[(s0 + ty + j) * Dc + d0 + tx];
    __syncthreads();
#pragma unroll
    for (int j = 0; j < 32; j += 8) Vt[(d0 + ty + j) * Sc + s0 + tx] = t[tx][ty + j];
}

// ---------------- GEMM (tf32 MMA): C[8192,512] = A[8192,512] @ W[512,512] ----
// sel 0/1/2: remap store into g_Q/g_K/g_V [bh][s][d]; sel 3: A:=g_ctx, plain store
__global__ __launch_bounds__(256) void gemm_mma(const float* __restrict__ A,
                                                float* __restrict__ Cplain, int sel)
{
    __shared__ unsigned As[128][36];
    __shared__ unsigned Bs[128][36];
    const float* Ap = (sel == 3) ? g_ctx : A;
    const float* Wt = g_Wt + sel * DMc * DMc;

    int tid = threadIdx.x;
    int w = tid >> 5, lane = tid & 31, gid = lane >> 2, qid = lane & 3;
    int warp_m = (w >> 2) * 64, warp_n = (w & 3) * 32;
    int m0 = blockIdx.y * 128, n0 = blockIdx.x * 128;

    float acc[4][4][4];
#pragma unroll
    for (int i = 0; i < 4; i++)
#pragma unroll
        for (int j = 0; j < 4; j++)
#pragma unroll
            for (int r = 0; r < 4; r++) acc[i][j][r] = 0.f;

    for (int kt = 0; kt < 512; kt += 32) {
#pragma unroll
        for (int u = 0; u < 16; u++) {
            int e = tid + 256 * u;
            int m = e >> 5, k = e & 31;
            As[m][k] = f2tf(Ap[(m0 + m) * 512 + kt + k]);
            Bs[m][k] = f2tf(Wt[(n0 + m) * 512 + kt + k]);
        }
        __syncthreads();
#pragma unroll
        for (int ks = 0; ks < 4; ks++) {
            unsigned a[4][4], b[4][2];
#pragma unroll
            for (int mf = 0; mf < 4; mf++) {
                int r = warp_m + mf * 16 + gid;
                a[mf][0] = As[r][ks * 8 + qid];
                a[mf][1] = As[r + 8][ks * 8 + qid];
                a[mf][2] = As[r][ks * 8 + qid + 4];
                a[mf][3] = As[r + 8][ks * 8 + qid + 4];
            }
#pragma unroll
            for (int nf = 0; nf < 4; nf++) {
                int r = warp_n + nf * 8 + gid;
                b[nf][0] = Bs[r][ks * 8 + qid];
                b[nf][1] = Bs[r][ks * 8 + qid + 4];
            }
#pragma unroll
            for (int mf = 0; mf < 4; mf++)
#pragma unroll
                for (int nf = 0; nf < 4; nf++)
                    mma8(acc[mf][nf], a[mf], b[nf]);
        }
        __syncthreads();
    }

#pragma unroll
    for (int mf = 0; mf < 4; mf++)
#pragma unroll
        for (int nf = 0; nf < 4; nf++) {
            int m = m0 + warp_m + mf * 16 + gid;
            int n = n0 + warp_n + nf * 8 + qid * 2;
            float2 lo = make_float2(acc[mf][nf][0], acc[mf][nf][1]);
            float2 hi = make_float2(acc[mf][nf][2], acc[mf][nf][3]);
            if (sel == 3) {
                *(float2*)&Cplain[m * 512 + n] = lo;
                *(float2*)&Cplain[(m + 8) * 512 + n] = hi;
            } else {
                float* dst = (sel == 0) ? g_Q : (sel == 1) ? g_K : g_V;
                int b_ = m >> 10, s = m & 1023;
                int h = n >> 6, d = n & 63;
                *(float2*)&dst[((b_ * Hc + h) * Sc + s) * Dc + d] = lo;
                *(float2*)&dst[((b_ * Hc + h) * Sc + s + 8) * Dc + d] = hi;
            }
        }
}

// ---------------- scores (tf32 MMA): S = QK^T/8 + edge, mask -> scratch ------
// grid (8 ktiles, 8 qtiles, 64 bh), block 256; tile 128x128, d=64 fully staged
__global__ __launch_bounds__(256) void scores_mma(const float* __restrict__ edge,
                                                  const int* __restrict__ mask)
{
    extern __shared__ unsigned sm_u[];
    unsigned (*Qs)[68] = (unsigned(*)[68])sm_u;
    unsigned (*Ks)[68] = (unsigned(*)[68])(sm_u + 128 * 68);

    int tid = threadIdx.x;
    int w = tid >> 5, lane = tid & 31, gid = lane >> 2, qid = lane & 3;
    int warp_m = (w >> 2) * 64, warp_n = (w & 3) * 32;
    int k0 = blockIdx.x * 128, q0 = blockIdx.y * 128;
    int bh = blockIdx.z;
    int b = bh >> 3;

    const float* Qg = g_Q + (bh * Sc + q0) * Dc;
    const float* Kg = g_K + (bh * Sc + k0) * Dc;
#pragma unroll
    for (int u = 0; u < 32; u++) {
        int e = tid + 256 * u;
        int r = e >> 6, d = e & 63;
        Qs[r][d] = f2tf(Qg[r * 64 + d]);
        Ks[r][d] = f2tf(Kg[r * 64 + d]);
    }
    __syncthreads();

    float acc[4][4][4];
#pragma unroll
    for (int i = 0; i < 4; i++)
#pragma unroll
        for (int j = 0; j < 4; j++)
#pragma unroll
            for (int r = 0; r < 4; r++) acc[i][j][r] = 0.f;

#pragma unroll
    for (int ks = 0; ks < 8; ks++) {
        unsigned a[4][4], bb[4][2];
#pragma unroll
        for (int mf = 0; mf < 4; mf++) {
            int r = warp_m + mf * 16 + gid;
            a[mf][0] = Qs[r][ks * 8 + qid];
            a[mf][1] = Qs[r + 8][ks * 8 + qid];
            a[mf][2] = Qs[r][ks * 8 + qid + 4];
            a[mf][3] = Qs[r + 8][ks * 8 + qid + 4];
        }
#pragma unroll
        for (int nf = 0; nf < 4; nf++) {
            int r = warp_n + nf * 8 + gid;
            bb[nf][0] = Ks[r][ks * 8 + qid];
            bb[nf][1] = Ks[r][ks * 8 + qid + 4];
        }
#pragma unroll
        for (int mf = 0; mf < 4; mf++)
#pragma unroll
            for (int nf = 0; nf < 4; nf++)
                mma8(acc[mf][nf], a[mf], bb[nf]);
    }

#pragma unroll
    for (int mf = 0; mf < 4; mf++)
#pragma unroll
        for (int nf = 0; nf < 4; nf++) {
            int q = q0 + warp_m + mf * 16 + gid;
            int kc = k0 + warp_n + nf * 8 + qid * 2;
#pragma unroll
            for (int half = 0; half < 2; half++) {
                int qq = q + half * 8;
                int rowe = (b * Sc + qq) * Sc;
                float2 ev = *(const float2*)&edge[rowe + kc];
                int2 mv = *(const int2*)&mask[rowe + kc];
                float c0 = acc[mf][nf][half * 2 + 0];
                float c1 = acc[mf][nf][half * 2 + 1];
                float2 o;
                o.x = mv.x ? -1e9f : c0 * 0.125f + ev.x;
                o.y = mv.y ? -1e9f : c1 * 0.125f + ev.y;
                *(float2*)&g_scores[(bh * Sc + qq) * Sc + kc] = o;
            }
        }
}

// ---------------- row stats (max, 1/sumexp) + head-avg -> d_out part 2 -------
__global__ __launch_bounds__(256) void rowstats_kernel(float* __restrict__ out_avg)
{
    __shared__ float red[8];
    int tid = threadIdx.x;
    int bq = blockIdx.x;
    int b = bq >> 10, q = bq & 1023;
    int lane = tid & 31, wid = tid >> 5;

    float4 av = make_float4(0.f, 0.f, 0.f, 0.f);
#pragma unroll 1
    for (int h = 0; h < 8; h++) {
        int row = (b * 8 + h) * 1024 + q;
        float4 v = *(const float4*)&g_scores[row * 1024 + tid * 4];

        float mx = fmaxf(fmaxf(v.x, v.y), fmaxf(v.z, v.w));
#pragma unroll
        for (int o = 16; o; o >>= 1) mx = fmaxf(mx, __shfl_xor_sync(0xffffffffu, mx, o));
        if (lane == 0) red[wid] = mx;
        __syncthreads();
        mx = red[0];
#pragma unroll
        for (int ww = 1; ww < 8; ww++) mx = fmaxf(mx, red[ww]);
        __syncthreads();

        float se = expf(v.x - mx) + expf(v.y - mx) + expf(v.z - mx) + expf(v.w - mx);
#pragma unroll
        for (int o = 16; o; o >>= 1) se += __shfl_xor_sync(0xffffffffu, se, o);
        if (lane == 0) red[wid] = se;
        __syncthreads();
        se = red[0] + red[1] + red[2] + red[3] + red[4] + red[5] + red[6] + red[7];
        __syncthreads();

        if (tid == 0) { g_m[row] = mx; g_linv[row] = 1.0f / se; }
        av.x += v.x; av.y += v.y; av.z += v.z; av.w += v.w;
    }
    av.x *= 0.125f; av.y *= 0.125f; av.z *= 0.125f; av.w *= 0.125f;
    *(float4*)&out_avg[bq * 1024 + tid * 4] = av;
}

// ---------------- AV (tf32 MMA): ctx[b,q,h*64+d] = softmax(S) @ V ------------
// grid (8 qtiles, 64 bh), block 256; block tile 128q x 64d, K chunks of 32
__global__ __launch_bounds__(256) void av_mma()
{
    __shared__ unsigned Ps[128][36];
    __shared__ unsigned Vs[64][36];
    __shared__ float ms[128], ls[128];

    int tid = threadIdx.x;
    int w = tid >> 5, lane = tid & 31, gid = lane >> 2, qid = lane & 3;
    int warp_m = (w >> 1) * 32, warp_n = (w & 1) * 32;
    int q0 = blockIdx.x * 128;
    int bh = blockIdx.y;
    int b = bh >> 3, h = bh & 7;

    if (tid < 128) {
        ms[tid] = g_m[bh * Sc + q0 + tid];
        ls[tid] = g_linv[bh * Sc + q0 + tid];
    }
    __syncthreads();

    float acc[2][4][4];
#pragma unroll
    for (int i = 0; i < 2; i++)
#pragma unroll
        for (int j = 0; j < 4; j++)
#pragma unroll
            for (int r = 0; r < 4; r++) acc[i][j][r] = 0.f;

    for (int kt = 0; kt < 1024; kt += 32) {
#pragma unroll
        for (int u = 0; u < 16; u++) {
            int e = tid + 256 * u;
            int q = e >> 5, kk = e & 31;
            float s = g_scores[(bh * Sc + q0 + q) * Sc + kt + kk];
            Ps[q][kk] = f2tf(__expf(s - ms[q]) * ls[q]);
        }
#pragma unroll
        for (int u = 0; u < 8; u++) {
            int e = tid + 256 * u;
            int d = e >> 5, kk = e & 31;
            Vs[d][kk] = f2tf(g_Vt[(bh * Dc + d) * Sc + kt + kk]);
        }
        __syncthreads();
#pragma unroll
        for (int ks = 0; ks < 4; ks++) {
            unsigned a[2][4], bb[4][2];
#pragma unroll
            for (int mf = 0; mf < 2; mf++) {
                int r = warp_m + mf * 16 + gid;
                a[mf][0] = Ps[r][ks * 8 + qid];
                a[mf][1] = Ps[r + 8][ks * 8 + qid];
                a[mf][2] = Ps[r][ks * 8 + qid + 4];
                a[mf][3] = Ps[r + 8][ks * 8 + qid + 4];
            }
#pragma unroll
            for (int nf = 0; nf < 4; nf++) {
                int r = warp_n + nf * 8 + gid;
                bb[nf][0] = Vs[r][ks * 8 + qid];
                bb[nf][1] = Vs[r][ks * 8 + qid + 4];
            }
#pragma unroll
            for (int mf = 0; mf < 2; mf++)
#pragma unroll
                for (int nf = 0; nf < 4; nf++)
                    mma8(acc[mf][nf], a[mf], bb[nf]);
        }
        __syncthreads();
    }

#pragma unroll
    for (int mf = 0; mf < 2; mf++)
#pragma unroll
        for (int nf = 0; nf < 4; nf++) {
            int q = q0 + warp_m + mf * 16 + gid;
            int dcol = warp_n + nf * 8 + qid * 2;
            float2 lo = make_float2(acc[mf][nf][0], acc[mf][nf][1]);
            float2 hi = make_float2(acc[mf][nf][2], acc[mf][nf][3]);
            *(float2*)&g_ctx[(b * Sc + q) * DMc + h * Dc + dcol] = lo;
            *(float2*)&g_ctx[(b * Sc + q + 8) * DMc + h * Dc + dcol] = hi;
        }
}

// ---------------- launch ------------------------------------------------------
extern "C" void kernel_launch(void* const* d_in, const int* in_sizes, int n_in,
                              void* d_out, int out_size)
{
    (void)in_sizes; (void)n_in; (void)out_size;
    const float* inQ  = (const float*)d_in[0];
    const float* inK  = (const float*)d_in[1];
    const float* inV  = (const float*)d_in[2];
    const int*   mask = (const int*)d_in[3];
    const float* edge = (const float*)d_in[4];
    const float* WQ   = (const float*)d_in[5];
    const float* WK   = (const float*)d_in[6];
    const float* WV   = (const float*)d_in[7];
    const float* Wfc  = (const float*)d_in[8];

    float* out     = (float*)d_out;
    float* out_avg = out + Bc * Sc * DMc;

    const int SC_SMEM = 2 * 128 * 68 * 4;   // 69632
    cudaFuncSetAttribute(scores_mma, cudaFuncAttributeMaxDynamicSharedMemorySize, SC_SMEM);

    transpose_w<<<dim3(16, 16, 4), dim3(32, 8)>>>(WQ, WK, WV, Wfc);

    dim3 gg(4, 64);
    gemm_mma<<<gg, 256>>>(inQ, nullptr, 0);
    gemm_mma<<<gg, 256>>>(inK, nullptr, 1);
    gemm_mma<<<gg, 256>>>(inV, nullptr, 2);

    transpose_v<<<dim3(32, 2, 64), dim3(32, 8)>>>();

    scores_mma<<<dim3(8, 8, 64), 256, SC_SMEM>>>(edge, mask);
    rowstats_kernel<<<8192, 256>>>(out_avg);
    av_mma<<<dim3(8, 64), 256>>>();

    gemm_mma<<<gg, 256>>>(nullptr, out, 3);
}

// round 5
// speedup vs baseline: 2.5119x; 1.3846x over previous
#include <cuda_runtime.h>

#define Bc 8
#define Sc 1024
#define DMc 512
#define Hc 8
#define Dc 64

// ---------------- device scratch ----------------
__device__ float g_Q[Bc*Hc*Sc*Dc];          // [bh][s][d]
__device__ float g_K[Bc*Hc*Sc*Dc];          // [bh][s][d]
__device__ float g_V[Bc*Hc*Sc*Dc];          // [bh][s][d]
__device__ float g_Vt[Bc*Hc*Dc*Sc];         // [bh][d][s]
__device__ float g_ctx[Bc*Sc*DMc];          // [b*s][512]
__device__ float g_Wt[4*DMc*DMc];           // [which][n][k]
__device__ float g_scores[Bc*Hc*Sc*Sc];     // [bh][q][k] (post edge+mask)
__device__ float g_m[Bc*Hc*Sc];
__device__ float g_linv[Bc*Hc*Sc];

__device__ __forceinline__ unsigned f2tf(float x) {
    unsigned u;
    asm("cvt.rna.tf32.f32 %0, %1;" : "=r"(u) : "f"(x));
    return u;
}

__device__ __forceinline__ void mma8(float* c, const unsigned* a, const unsigned* b) {
    asm volatile(
        "mma.sync.aligned.m16n8k8.row.col.f32.tf32.tf32.f32 "
        "{%0,%1,%2,%3}, {%4,%5,%6,%7}, {%8,%9}, {%0,%1,%2,%3};"
        : "+f"(c[0]), "+f"(c[1]), "+f"(c[2]), "+f"(c[3])
        : "r"(a[0]), "r"(a[1]), "r"(a[2]), "r"(a[3]), "r"(b[0]), "r"(b[1]));
}

// ---------------- transpose W: g_Wt[i][n][k] = W_i[k][n] ----------------
__global__ void transpose_w(const float* __restrict__ W0, const float* __restrict__ W1,
                            const float* __restrict__ W2, const float* __restrict__ W3)
{
    __shared__ float t[32][33];
    const float* W = (blockIdx.z == 0) ? W0 : (blockIdx.z == 1) ? W1 : (blockIdx.z == 2) ? W2 : W3;
    float* out = g_Wt + blockIdx.z * DMc * DMc;
    int x0 = blockIdx.x * 32, y0 = blockIdx.y * 32;
    int tx = threadIdx.x, ty = threadIdx.y;
#pragma unroll
    for (int j = 0; j < 32; j += 8) t[ty + j][tx] = W[(y0 + ty + j) * DMc + x0 + tx];
    __syncthreads();
#pragma unroll
    for (int j = 0; j < 32; j += 8) out[(x0 + ty + j) * DMc + y0 + tx] = t[tx][ty + j];
}

// ---------------- transpose V: g_Vt[bh][d][s] = g_V[bh][s][d] ----------------
__global__ void transpose_v()
{
    __shared__ float t[32][33];
    int bh = blockIdx.z;
    int s0 = blockIdx.x * 32, d0 = blockIdx.y * 32;
    const float* V = g_V + bh * Sc * Dc;
    float* Vt = g_Vt + bh * Dc * Sc;
    int tx = threadIdx.x, ty = threadIdx.y;
#pragma unroll
    for (int j = 0; j < 32; j += 8) t[ty + j][tx] = V[(s0 + ty + j) * Dc + d0 + tx];
    __syncthreads();
#pragma unroll
    for (int j = 0; j < 32; j += 8) Vt[(d0 + ty + j) * Sc + s0 + tx] = t[tx][ty + j];
}

// ---------------- GEMM (tf32 MMA, double-buffered): C = A[8192,512] @ W -----
// sel 0/1/2: remap store into g_Q/g_K/g_V [bh][s][d]; sel 3: A:=g_ctx, plain store
__global__ __launch_bounds__(256) void gemm_mma(const float* __restrict__ A,
                                                float* __restrict__ Cplain, int sel)
{
    extern __shared__ unsigned dyn[];
    // layout: [buf][A(128x36) | B(128x36)]
    const float* Ap = (sel == 3) ? g_ctx : A;
    const float* Wt = g_Wt + sel * DMc * DMc;

    int tid = threadIdx.x;
    int w = tid >> 5, lane = tid & 31, gid = lane >> 2, qid = lane & 3;
    int warp_m = (w >> 2) * 64, warp_n = (w & 3) * 32;
    int m0 = blockIdx.y * 128, n0 = blockIdx.x * 128;

    float2 ra[8], rb[8];
    int sm_ = (tid + 0) >> 4;          // row index base per u handled in loop
    (void)sm_;

    float acc[4][4][4];
#pragma unroll
    for (int i = 0; i < 4; i++)
#pragma unroll
        for (int j = 0; j < 4; j++)
#pragma unroll
            for (int r = 0; r < 4; r++) acc[i][j][r] = 0.f;

    // prologue: kt = 0
#pragma unroll
    for (int u = 0; u < 8; u++) {
        int e = tid + 256 * u;
        int m = e >> 4, k2 = e & 15;
        ra[u] = *(const float2*)&Ap[(m0 + m) * 512 + 2 * k2];
        rb[u] = *(const float2*)&Wt[(n0 + m) * 512 + 2 * k2];
    }
#pragma unroll
    for (int u = 0; u < 8; u++) {
        int e = tid + 256 * u;
        int m = e >> 4, k2 = e & 15;
        unsigned* Asb = dyn;
        unsigned* Bsb = dyn + 128 * 36;
        *(uint2*)&Asb[m * 36 + 2 * k2] = make_uint2(f2tf(ra[u].x), f2tf(ra[u].y));
        *(uint2*)&Bsb[m * 36 + 2 * k2] = make_uint2(f2tf(rb[u].x), f2tf(rb[u].y));
    }
    __syncthreads();

    int buf = 0;
    for (int kt = 0; kt < 512; kt += 32) {
        bool more = (kt + 32) < 512;
        if (more) {
#pragma unroll
            for (int u = 0; u < 8; u++) {
                int e = tid + 256 * u;
                int m = e >> 4, k2 = e & 15;
                ra[u] = *(const float2*)&Ap[(m0 + m) * 512 + kt + 32 + 2 * k2];
                rb[u] = *(const float2*)&Wt[(n0 + m) * 512 + kt + 32 + 2 * k2];
            }
        }
        {
            unsigned* Asb = dyn + buf * 2 * 128 * 36;
            unsigned* Bsb = Asb + 128 * 36;
#pragma unroll
            for (int ks = 0; ks < 4; ks++) {
                unsigned a[4][4], b[4][2];
#pragma unroll
                for (int mf = 0; mf < 4; mf++) {
                    int r = warp_m + mf * 16 + gid;
                    a[mf][0] = Asb[r * 36 + ks * 8 + qid];
                    a[mf][1] = Asb[(r + 8) * 36 + ks * 8 + qid];
                    a[mf][2] = Asb[r * 36 + ks * 8 + qid + 4];
                    a[mf][3] = Asb[(r + 8) * 36 + ks * 8 + qid + 4];
                }
#pragma unroll
                for (int nf = 0; nf < 4; nf++) {
                    int r = warp_n + nf * 8 + gid;
                    b[nf][0] = Bsb[r * 36 + ks * 8 + qid];
                    b[nf][1] = Bsb[r * 36 + ks * 8 + qid + 4];
                }
#pragma unroll
                for (int mf = 0; mf < 4; mf++)
#pragma unroll
                    for (int nf = 0; nf < 4; nf++)
                        mma8(acc[mf][nf], a[mf], b[nf]);
            }
        }
        if (more) {
            unsigned* Asb = dyn + (buf ^ 1) * 2 * 128 * 36;
            unsigned* Bsb = Asb + 128 * 36;
#pragma unroll
            for (int u = 0; u < 8; u++) {
                int e = tid + 256 * u;
                int m = e >> 4, k2 = e & 15;
                *(uint2*)&Asb[m * 36 + 2 * k2] = make_uint2(f2tf(ra[u].x), f2tf(ra[u].y));
                *(uint2*)&Bsb[m * 36 + 2 * k2] = make_uint2(f2tf(rb[u].x), f2tf(rb[u].y));
            }
        }
        __syncthreads();
        buf ^= 1;
    }

#pragma unroll
    for (int mf = 0; mf < 4; mf++)
#pragma unroll
        for (int nf = 0; nf < 4; nf++) {
            int m = m0 + warp_m + mf * 16 + gid;
            int n = n0 + warp_n + nf * 8 + qid * 2;
            float2 lo = make_float2(acc[mf][nf][0], acc[mf][nf][1]);
            float2 hi = make_float2(acc[mf][nf][2], acc[mf][nf][3]);
            if (sel == 3) {
                *(float2*)&Cplain[m * 512 + n] = lo;
                *(float2*)&Cplain[(m + 8) * 512 + n] = hi;
            } else {
                float* dst = (sel == 0) ? g_Q : (sel == 1) ? g_K : g_V;
                int b_ = m >> 10, s = m & 1023;
                int h = n >> 6, d = n & 63;
                *(float2*)&dst[((b_ * Hc + h) * Sc + s) * Dc + d] = lo;
                *(float2*)&dst[((b_ * Hc + h) * Sc + s + 8) * Dc + d] = hi;
            }
        }
}

// ---------------- scores (tf32 MMA): S = QK^T/8 + edge, mask -> scratch ------
__global__ __launch_bounds__(256) void scores_mma(const float* __restrict__ edge,
                                                  const int* __restrict__ mask)
{
    extern __shared__ unsigned sm_u[];
    unsigned (*Qs)[68] = (unsigned(*)[68])sm_u;
    unsigned (*Ks)[68] = (unsigned(*)[68])(sm_u + 128 * 68);

    int tid = threadIdx.x;
    int w = tid >> 5, lane = tid & 31, gid = lane >> 2, qid = lane & 3;
    int warp_m = (w >> 2) * 64, warp_n = (w & 3) * 32;
    int k0 = blockIdx.x * 128, q0 = blockIdx.y * 128;
    int bh = blockIdx.z;
    int b = bh >> 3;

    const float* Qg = g_Q + (bh * Sc + q0) * Dc;
    const float* Kg = g_K + (bh * Sc + k0) * Dc;
#pragma unroll
    for (int u = 0; u < 16; u++) {
        int e = tid + 256 * u;
        int r = e >> 5, k2 = e & 31;
        float2 qv = *(const float2*)&Qg[r * 64 + 2 * k2];
        float2 kv = *(const float2*)&Kg[r * 64 + 2 * k2];
        *(uint2*)&Qs[r][2 * k2] = make_uint2(f2tf(qv.x), f2tf(qv.y));
        *(uint2*)&Ks[r][2 * k2] = make_uint2(f2tf(kv.x), f2tf(kv.y));
    }
    __syncthreads();

    float acc[4][4][4];
#pragma unroll
    for (int i = 0; i < 4; i++)
#pragma unroll
        for (int j = 0; j < 4; j++)
#pragma unroll
            for (int r = 0; r < 4; r++) acc[i][j][r] = 0.f;

#pragma unroll
    for (int ks = 0; ks < 8; ks++) {
        unsigned a[4][4], bb[4][2];
#pragma unroll
        for (int mf = 0; mf < 4; mf++) {
            int r = warp_m + mf * 16 + gid;
            a[mf][0] = Qs[r][ks * 8 + qid];
            a[mf][1] = Qs[r + 8][ks * 8 + qid];
            a[mf][2] = Qs[r][ks * 8 + qid + 4];
            a[mf][3] = Qs[r + 8][ks * 8 + qid + 4];
        }
#pragma unroll
        for (int nf = 0; nf < 4; nf++) {
            int r = warp_n + nf * 8 + gid;
            bb[nf][0] = Ks[r][ks * 8 + qid];
            bb[nf][1] = Ks[r][ks * 8 + qid + 4];
        }
#pragma unroll
        for (int mf = 0; mf < 4; mf++)
#pragma unroll
            for (int nf = 0; nf < 4; nf++)
                mma8(acc[mf][nf], a[mf], bb[nf]);
    }

#pragma unroll
    for (int mf = 0; mf < 4; mf++)
#pragma unroll
        for (int nf = 0; nf < 4; nf++) {
            int q = q0 + warp_m + mf * 16 + gid;
            int kc = k0 + warp_n + nf * 8 + qid * 2;
#pragma unroll
            for (int half = 0; half < 2; half++) {
                int qq = q + half * 8;
                int rowe = (b * Sc + qq) * Sc;
                float2 ev = *(const float2*)&edge[rowe + kc];
                int2 mv = *(const int2*)&mask[rowe + kc];
                float c0 = acc[mf][nf][half * 2 + 0];
                float c1 = acc[mf][nf][half * 2 + 1];
                float2 o;
                o.x = mv.x ? -1e9f : c0 * 0.125f + ev.x;
                o.y = mv.y ? -1e9f : c1 * 0.125f + ev.y;
                *(float2*)&g_scores[(bh * Sc + qq) * Sc + kc] = o;
            }
        }
}

// ---------------- row stats (max, 1/sumexp) + head-avg -> d_out part 2 -------
__global__ __launch_bounds__(256) void rowstats_kernel(float* __restrict__ out_avg)
{
    __shared__ float red[8];
    int tid = threadIdx.x;
    int bq = blockIdx.x;
    int b = bq >> 10, q = bq & 1023;
    int lane = tid & 31, wid = tid >> 5;

    float4 av = make_float4(0.f, 0.f, 0.f, 0.f);
#pragma unroll 1
    for (int h = 0; h < 8; h++) {
        int row = (b * 8 + h) * 1024 + q;
        float4 v = *(const float4*)&g_scores[row * 1024 + tid * 4];

        float mx = fmaxf(fmaxf(v.x, v.y), fmaxf(v.z, v.w));
#pragma unroll
        for (int o = 16; o; o >>= 1) mx = fmaxf(mx, __shfl_xor_sync(0xffffffffu, mx, o));
        if (lane == 0) red[wid] = mx;
        __syncthreads();
        mx = red[0];
#pragma unroll
        for (int ww = 1; ww < 8; ww++) mx = fmaxf(mx, red[ww]);
        __syncthreads();

        float se = __expf(v.x - mx) + __expf(v.y - mx) + __expf(v.z - mx) + __expf(v.w - mx);
#pragma unroll
        for (int o = 16; o; o >>= 1) se += __shfl_xor_sync(0xffffffffu, se, o);
        if (lane == 0) red[wid] = se;
        __syncthreads();
        se = red[0] + red[1] + red[2] + red[3] + red[4] + red[5] + red[6] + red[7];
        __syncthreads();

        if (tid == 0) { g_m[row] = mx; g_linv[row] = 1.0f / se; }
        av.x += v.x; av.y += v.y; av.z += v.z; av.w += v.w;
    }
    av.x *= 0.125f; av.y *= 0.125f; av.z *= 0.125f; av.w *= 0.125f;
    *(float4*)&out_avg[bq * 1024 + tid * 4] = av;
}

// ---------------- AV (tf32 MMA, double-buffered) -----------------------------
// grid (8 qtiles, 64 bh), block 256; block tile 128q x 64d, K chunks of 32
__global__ __launch_bounds__(256) void av_mma()
{
    extern __shared__ unsigned dynv[];
    // layout: [buf][P(128x36) | V(64x36)]  -> per buf 6912 words
    __shared__ float ms[128], ls[128];

    int tid = threadIdx.x;
    int w = tid >> 5, lane = tid & 31, gid = lane >> 2, qid = lane & 3;
    int warp_m = (w >> 1) * 32, warp_n = (w & 1) * 32;
    int q0 = blockIdx.x * 128;
    int bh = blockIdx.y;
    int b = bh >> 3, h = bh & 7;

    if (tid < 128) {
        ms[tid] = g_m[bh * Sc + q0 + tid];
        ls[tid] = g_linv[bh * Sc + q0 + tid];
    }
    __syncthreads();

    float2 rp[8], rv[4];

    float acc[2][4][4];
#pragma unroll
    for (int i = 0; i < 2; i++)
#pragma unroll
        for (int j = 0; j < 4; j++)
#pragma unroll
            for (int r = 0; r < 4; r++) acc[i][j][r] = 0.f;

    // prologue kt = 0
#pragma unroll
    for (int u = 0; u < 8; u++) {
        int e = tid + 256 * u;
        int q = e >> 4, k2 = e & 15;
        rp[u] = *(const float2*)&g_scores[(bh * Sc + q0 + q) * Sc + 2 * k2];
    }
#pragma unroll
    for (int u = 0; u < 4; u++) {
        int e = tid + 256 * u;
        int d = e >> 4, k2 = e & 15;
        rv[u] = *(const float2*)&g_Vt[(bh * Dc + d) * Sc + 2 * k2];
    }
    {
        unsigned* Pb = dynv;
        unsigned* Vb = dynv + 128 * 36;
#pragma unroll
        for (int u = 0; u < 8; u++) {
            int e = tid + 256 * u;
            int q = e >> 4, k2 = e & 15;
            float l = ls[q], m = ms[q];
            *(uint2*)&Pb[q * 36 + 2 * k2] =
                make_uint2(f2tf(__expf(rp[u].x - m) * l), f2tf(__expf(rp[u].y - m) * l));
        }
#pragma unroll
        for (int u = 0; u < 4; u++) {
            int e = tid + 256 * u;
            int d = e >> 4, k2 = e & 15;
            *(uint2*)&Vb[d * 36 + 2 * k2] = make_uint2(f2tf(rv[u].x), f2tf(rv[u].y));
        }
    }
    __syncthreads();

    int buf = 0;
    for (int kt = 0; kt < 1024; kt += 32) {
        bool more = (kt + 32) < 1024;
        if (more) {
#pragma unroll
            for (int u = 0; u < 8; u++) {
                int e = tid + 256 * u;
                int q = e >> 4, k2 = e & 15;
                rp[u] = *(const float2*)&g_scores[(bh * Sc + q0 + q) * Sc + kt + 32 + 2 * k2];
            }
#pragma unroll
            for (int u = 0; u < 4; u++) {
                int e = tid + 256 * u;
                int d = e >> 4, k2 = e & 15;
                rv[u] = *(const float2*)&g_Vt[(bh * Dc + d) * Sc + kt + 32 + 2 * k2];
            }
        }
        {
            unsigned* Pb = dynv + buf * (128 + 64) * 36;
            unsigned* Vb = Pb + 128 * 36;
#pragma unroll
            for (int ks = 0; ks < 4; ks++) {
                unsigned a[2][4], bb[4][2];
#pragma unroll
                for (int mf = 0; mf < 2; mf++) {
                    int r = warp_m + mf * 16 + gid;
                    a[mf][0] = Pb[r * 36 + ks * 8 + qid];
                    a[mf][1] = Pb[(r + 8) * 36 + ks * 8 + qid];
                    a[mf][2] = Pb[r * 36 + ks * 8 + qid + 4];
                    a[mf][3] = Pb[(r + 8) * 36 + ks * 8 + qid + 4];
                }
#pragma unroll
                for (int nf = 0; nf < 4; nf++) {
                    int r = warp_n + nf * 8 + gid;
                    bb[nf][0] = Vb[r * 36 + ks * 8 + qid];
                    bb[nf][1] = Vb[r * 36 + ks * 8 + qid + 4];
                }
#pragma unroll
                for (int mf = 0; mf < 2; mf++)
#pragma unroll
                    for (int nf = 0; nf < 4; nf++)
                        mma8(acc[mf][nf], a[mf], bb[nf]);
            }
        }
        if (more) {
            unsigned* Pb = dynv + (buf ^ 1) * (128 + 64) * 36;
            unsigned* Vb = Pb + 128 * 36;
#pragma unroll
            for (int u = 0; u < 8; u++) {
                int e = tid + 256 * u;
                int q = e >> 4, k2 = e & 15;
                float l = ls[q], m = ms[q];
                *(uint2*)&Pb[q * 36 + 2 * k2] =
                    make_uint2(f2tf(__expf(rp[u].x - m) * l), f2tf(__expf(rp[u].y - m) * l));
            }
#pragma unroll
            for (int u = 0; u < 4; u++) {
                int e = tid + 256 * u;
                int d = e >> 4, k2 = e & 15;
                *(uint2*)&Vb[d * 36 + 2 * k2] = make_uint2(f2tf(rv[u].x), f2tf(rv[u].y));
            }
        }
        __syncthreads();
        buf ^= 1;
    }

#pragma unroll
    for (int mf = 0; mf < 2; mf++)
#pragma unroll
        for (int nf = 0; nf < 4; nf++) {
            int q = q0 + warp_m + mf * 16 + gid;
            int dcol = warp_n + nf * 8 + qid * 2;
            float2 lo = make_float2(acc[mf][nf][0], acc[mf][nf][1]);
            float2 hi = make_float2(acc[mf][nf][2], acc[mf][nf][3]);
            *(float2*)&g_ctx[(b * Sc + q) * DMc + h * Dc + dcol] = lo;
            *(float2*)&g_ctx[(b * Sc + q + 8) * DMc + h * Dc + dcol] = hi;
        }
}

// ---------------- launch ------------------------------------------------------
extern "C" void kernel_launch(void* const* d_in, const int* in_sizes, int n_in,
                              void* d_out, int out_size)
{
    (void)in_sizes; (void)n_in; (void)out_size;
    const float* inQ  = (const float*)d_in[0];
    const float* inK  = (const float*)d_in[1];
    const float* inV  = (const float*)d_in[2];
    const int*   mask = (const int*)d_in[3];
    const float* edge = (const float*)d_in[4];
    const float* WQ   = (const float*)d_in[5];
    const float* WK   = (const float*)d_in[6];
    const float* WV   = (const float*)d_in[7];
    const float* Wfc  = (const float*)d_in[8];

    float* out     = (float*)d_out;
    float* out_avg = out + Bc * Sc * DMc;

    const int GEMM_SMEM = 2 * 2 * 128 * 36 * 4;            // 73728
    const int SC_SMEM   = 2 * 128 * 68 * 4;                // 69632
    const int AV_SMEM   = 2 * (128 + 64) * 36 * 4;         // 55296
    cudaFuncSetAttribute(gemm_mma,   cudaFuncAttributeMaxDynamicSharedMemorySize, GEMM_SMEM);
    cudaFuncSetAttribute(scores_mma, cudaFuncAttributeMaxDynamicSharedMemorySize, SC_SMEM);
    cudaFuncSetAttribute(av_mma,     cudaFuncAttributeMaxDynamicSharedMemorySize, AV_SMEM);

    transpose_w<<<dim3(16, 16, 4), dim3(32, 8)>>>(WQ, WK, WV, Wfc);

    dim3 gg(4, 64);
    gemm_mma<<<gg, 256, GEMM_SMEM>>>(inQ, nullptr, 0);
    gemm_mma<<<gg, 256, GEMM_SMEM>>>(inK, nullptr, 1);
    gemm_mma<<<gg, 256, GEMM_SMEM>>>(inV, nullptr, 2);

    transpose_v<<<dim3(32, 2, 64), dim3(32, 8)>>>();

    scores_mma<<<dim3(8, 8, 64), 256, SC_SMEM>>>(edge, mask);
    rowstats_kernel<<<8192, 256>>>(out_avg);
    av_mma<<<dim3(8, 64), 256, AV_SMEM>>>();

    gemm_mma<<<gg, 256, GEMM_SMEM>>>(nullptr, out, 3);
}